// round 8
// baseline (speedup 1.0000x reference)
#include <cuda_runtime.h>
#include <math.h>

#define BATCH 4
#define SEQ   2048
#define DIMN  1024
#define HEADS 16
#define DHEAD 64
#define ROWS  (BATCH*SEQ)      /* 8192 */
#define QKV_N (3*DIMN)         /* 3072 */

// Scratch (allocation-free rule: __device__ globals)
static __device__ float g_xn[(size_t)ROWS*DIMN];     // LN out, k-perm8'd cols
static __device__ float g_qkv[(size_t)ROWS*QKV_N];   // K cols perm8'd, V cols perm16'd
static __device__ float g_attn[(size_t)ROWS*DIMN];   // attn out, k-perm8'd cols
static __device__ float g_wq[(size_t)DIMN*QKV_N];    // w_qkv^T, k-perm8'd, tf32
static __device__ float g_wo[(size_t)DIMN*DIMN];     // w_out^T, k-perm8'd, tf32

// ---------------------------------------------------------------------------
__device__ __forceinline__ unsigned f2tf(float x) {
    unsigned r;
    asm("cvt.rna.tf32.f32 %0, %1;" : "=r"(r) : "f"(x));
    return r;
}

__device__ __forceinline__ float fex2(float x) {   // 2^x, clamped below
    float r;
    x = fmaxf(x, -126.f);
    asm("ex2.approx.ftz.f32 %0, %1;" : "=f"(r) : "f"(x));
    return r;
}

// within-8 perm: (x, x+4) -> (2x', 2x'+1)
__device__ __forceinline__ int perm8(int c) {
    return (c & ~7) | ((c & 3) << 1) | ((c >> 2) & 1);
}

// qkv column permutation applied by gemm1 epilogue (N dim of gemm1):
//  K region (1024..2047): perm8 ; V region (2048..3071): within-16 (d,d+8)->(2d',2d'+1)
__device__ __forceinline__ int permcol(int c) {
    int reg = c >> 10;
    if (reg == 1) return perm8(c);
    if (reg == 2) return (c & ~15) | ((c & 7) << 1) | ((c >> 3) & 1);
    return c;
}

__device__ __forceinline__ void mma_tf32(float& c0, float& c1, float& c2, float& c3,
                                         unsigned a0, unsigned a1, unsigned a2, unsigned a3,
                                         unsigned b0, unsigned b1) {
    asm volatile(
        "mma.sync.aligned.m16n8k8.row.col.f32.tf32.tf32.f32 "
        "{%0,%1,%2,%3}, {%4,%5,%6,%7}, {%8,%9}, {%0,%1,%2,%3};\n"
        : "+f"(c0), "+f"(c1), "+f"(c2), "+f"(c3)
        : "r"(a0), "r"(a1), "r"(a2), "r"(a3), "r"(b0), "r"(b1));
}

#define CP_ASYNC16(dst, src) \
    asm volatile("cp.async.cg.shared.global [%0], [%1], 16;\n" :: "r"(dst), "l"(src))

// ---------------------------------------------------------------------------
// Weight preprocess: dst[n][perm8(k)] = tf32(src[k][n])   (transpose+perm+round)
// ---------------------------------------------------------------------------
__global__ __launch_bounds__(256) void tpose_cvt(const float* __restrict__ src,
                                                 float* __restrict__ dst,
                                                 int K, int N) {
    __shared__ float t[32][33];
    const int k0 = blockIdx.x * 32, n0 = blockIdx.y * 32;
    const int x = threadIdx.x & 31, y = threadIdx.x >> 5;
    #pragma unroll
    for (int j = 0; j < 4; j++)
        t[y + 8 * j][x] = src[(size_t)(k0 + y + 8 * j) * N + n0 + x];
    __syncthreads();
    const int xp = perm8(x);
    #pragma unroll
    for (int j = 0; j < 4; j++)
        dst[(size_t)(n0 + y + 8 * j) * K + k0 + xp] =
            __uint_as_float(f2tf(t[x][y + 8 * j]));
}

// ---------------------------------------------------------------------------
// LayerNorm: one block per row; output tf32-rounded, columns perm8'd
// ---------------------------------------------------------------------------
__global__ __launch_bounds__(256) void ln_kernel(const float* __restrict__ x,
                                                 const float* __restrict__ gamma,
                                                 const float* __restrict__ beta) {
    __shared__ float red[16];
    const int row = blockIdx.x;
    const int t = threadIdx.x;
    const float* xr = x + (size_t)row * DIMN;
    float4 v = *(const float4*)(xr + t * 4);
    float s = v.x + v.y + v.z + v.w;
    float q = v.x*v.x + v.y*v.y + v.z*v.z + v.w*v.w;
    #pragma unroll
    for (int o = 16; o; o >>= 1) {
        s += __shfl_xor_sync(0xffffffffu, s, o);
        q += __shfl_xor_sync(0xffffffffu, q, o);
    }
    if ((t & 31) == 0) { red[t >> 5] = s; red[8 + (t >> 5)] = q; }
    __syncthreads();
    if (t < 32) {
        float ss = (t < 8) ? red[t] : 0.f;
        float qq = (t < 8) ? red[8 + t] : 0.f;
        #pragma unroll
        for (int o = 4; o; o >>= 1) {
            ss += __shfl_xor_sync(0xffffffffu, ss, o);
            qq += __shfl_xor_sync(0xffffffffu, qq, o);
        }
        if (t == 0) { red[0] = ss; red[1] = qq; }
    }
    __syncthreads();
    const float mean = red[0] * (1.f / DIMN);
    const float var  = red[1] * (1.f / DIMN) - mean * mean;
    const float inv  = rsqrtf(var + 1e-5f);
    float4 g = *(const float4*)(gamma + t * 4);
    float4 b = *(const float4*)(beta  + t * 4);
    float o4[4];
    o4[0] = (v.x - mean) * inv * g.x + b.x;
    o4[1] = (v.y - mean) * inv * g.y + b.y;
    o4[2] = (v.z - mean) * inv * g.z + b.z;
    o4[3] = (v.w - mean) * inv * g.w + b.w;
    float* dr = g_xn + (size_t)row * DIMN;
    #pragma unroll
    for (int j = 0; j < 4; j++)
        dr[perm8(t * 4 + j)] = __uint_as_float(f2tf(o4[j]));
}

// ---------------------------------------------------------------------------
// tf32 tensor-core GEMM v2: A[m][kperm8], B = W^T[n][kperm8]; all fragment
// loads are conflict-free LDS.64 (stride 40 -> start banks 8g+2tg).
// mode 0: fp32 out +bias. mode 1: tf32-rounded out, qkv col permutation.
// ---------------------------------------------------------------------------
#define GSTR 40
#define GBUF (128*GSTR)   /* 5120 floats per stage per matrix */

__global__ __launch_bounds__(256) void gemm_tc(const float* __restrict__ A,
                                               const float* __restrict__ B,
                                               const float* __restrict__ bias,
                                               float* __restrict__ C,
                                               int M, int N, int K, int mode) {
    extern __shared__ float sm[];
    float* As = sm;                  // [2][128][GSTR]
    float* Bs = sm + 2 * GBUF;       // [2][128][GSTR]

    const int tid = threadIdx.x;
    const int wid = tid >> 5, lane = tid & 31;
    const int g = lane >> 2, tg = lane & 3;
    const int wm = wid >> 1, wn = wid & 1;
    const int bm = blockIdx.y * 128, bn = blockIdx.x * 128;

    float c[2][8][4] = {};

    auto loadAB = [&](int buf, int k0) {
        unsigned abase = (unsigned)__cvta_generic_to_shared(As + buf * GBUF);
        unsigned bbase = (unsigned)__cvta_generic_to_shared(Bs + buf * GBUF);
        #pragma unroll
        for (int p = 0; p < 4; p++) {
            int idx = tid + p * 256;
            int r = idx >> 3, cc = (idx & 7) * 4;
            CP_ASYNC16(abase + (r * GSTR + cc) * 4, A + (size_t)(bm + r) * K + k0 + cc);
        }
        #pragma unroll
        for (int p = 0; p < 4; p++) {
            int idx = tid + p * 256;
            int r = idx >> 3, cc = (idx & 7) * 4;
            CP_ASYNC16(bbase + (r * GSTR + cc) * 4, B + (size_t)(bn + r) * K + k0 + cc);
        }
    };

    const int nk = K / 32;
    loadAB(0, 0);
    asm volatile("cp.async.commit_group;\n");

    for (int kb = 0; kb < nk; kb++) {
        if (kb + 1 < nk) {
            loadAB((kb + 1) & 1, (kb + 1) * 32);
            asm volatile("cp.async.commit_group;\n");
            asm volatile("cp.async.wait_group 1;\n");
        } else {
            asm volatile("cp.async.wait_group 0;\n");
        }
        __syncthreads();

        const float* Ab = As + (kb & 1) * GBUF;
        const float* Bb = Bs + (kb & 1) * GBUF;
        #pragma unroll
        for (int ks = 0; ks < 4; ks++) {
            const int kk = ks * 8 + 2 * tg;
            float2 av[2][2];
            #pragma unroll
            for (int mt = 0; mt < 2; mt++) {
                int r0 = wm * 32 + mt * 16;
                av[mt][0] = *(const float2*)&Ab[(r0 + g)     * GSTR + kk];  // a0,a2
                av[mt][1] = *(const float2*)&Ab[(r0 + g + 8) * GSTR + kk];  // a1,a3
            }
            #pragma unroll
            for (int nt = 0; nt < 8; nt++) {
                float2 bv = *(const float2*)&Bb[(wn * 64 + nt * 8 + g) * GSTR + kk];
                #pragma unroll
                for (int mt = 0; mt < 2; mt++)
                    mma_tf32(c[mt][nt][0], c[mt][nt][1], c[mt][nt][2], c[mt][nt][3],
                             __float_as_uint(av[mt][0].x), __float_as_uint(av[mt][1].x),
                             __float_as_uint(av[mt][0].y), __float_as_uint(av[mt][1].y),
                             __float_as_uint(bv.x), __float_as_uint(bv.y));
            }
        }
        __syncthreads();
    }

    #pragma unroll
    for (int mt = 0; mt < 2; mt++) {
        int r0 = bm + wm * 32 + mt * 16 + g;
        #pragma unroll
        for (int nt = 0; nt < 8; nt++) {
            int col = bn + wn * 64 + nt * 8 + 2 * tg;
            if (mode == 0) {
                float b0 = bias ? bias[col] : 0.f, b1 = bias ? bias[col + 1] : 0.f;
                *(float2*)(C + (size_t)r0 * N + col) =
                    make_float2(c[mt][nt][0] + b0, c[mt][nt][1] + b1);
                *(float2*)(C + (size_t)(r0 + 8) * N + col) =
                    make_float2(c[mt][nt][2] + b0, c[mt][nt][3] + b1);
            } else {
                int c0 = permcol(col), c1 = permcol(col + 1);
                C[(size_t)r0 * N + c0]       = __uint_as_float(f2tf(c[mt][nt][0]));
                C[(size_t)r0 * N + c1]       = __uint_as_float(f2tf(c[mt][nt][1]));
                C[(size_t)(r0 + 8) * N + c0] = __uint_as_float(f2tf(c[mt][nt][2]));
                C[(size_t)(r0 + 8) * N + c1] = __uint_as_float(f2tf(c[mt][nt][3]));
            }
        }
    }
}

// ---------------------------------------------------------------------------
// Flash attention v4 (R7, proven): output columns now perm8'd for gemm2.
// ---------------------------------------------------------------------------
#define FSK 72
#define FSV 72
#define FSP 68
#define KBUF (64*FSK)
#define VBUF (64*FSV)
#define FL_SMF (2*KBUF + 2*VBUF + 128*FSP)    /* 27136 floats = 108544 B */

__global__ __launch_bounds__(256, 2) void flash_tc4(const float* __restrict__ qkv,
                                                    float* __restrict__ attn) {
    extern __shared__ float sm[];
    float* Ks = sm;                    // [2][64][FSK], perm8 cols
    float* Vs = sm + 2 * KBUF;         // [2][64][FSV], perm16 cols
    float* Ps = sm + 2 * KBUF + 2 * VBUF;  // [128][FSP]; doubles as Q stage

    const int tid = threadIdx.x;
    const int wid = tid >> 5, lane = tid & 31;
    const int g = lane >> 2, tg = lane & 3;
    const int qr = wid * 16;
    const int qt = blockIdx.x;
    const int bh = blockIdx.y;
    const int b = bh >> 4, h = bh & 15;
    const size_t base = (size_t)b * SEQ;
    const int qoff = h * DHEAD;
    const int koff = DIMN + h * DHEAD;
    const int voff = 2 * DIMN + h * DHEAD;

    #pragma unroll
    for (int p = 0; p < 8; p++) {
        int idx = tid + p * 256;
        int row = idx >> 4, c4 = (idx & 15) * 4;
        *(float4*)(Ps + row * FSP + c4) =
            *(const float4*)(qkv + (base + qt * 128 + row) * QKV_N + qoff + c4);
    }
    __syncthreads();
    unsigned qf[8][4];
    {
        const float QS = 0.125f * 1.4426950408889634f;
        const int r0 = (qr + g) * FSP, r1 = (qr + g + 8) * FSP;
        #pragma unroll
        for (int ks = 0; ks < 8; ks++) {
            int c = ks * 8 + tg;
            qf[ks][0] = f2tf(Ps[r0 + c]     * QS);
            qf[ks][1] = f2tf(Ps[r1 + c]     * QS);
            qf[ks][2] = f2tf(Ps[r0 + c + 4] * QS);
            qf[ks][3] = f2tf(Ps[r1 + c + 4] * QS);
        }
    }

    auto loadKV = [&](int buf, int kt) {
        unsigned kbase = (unsigned)__cvta_generic_to_shared(Ks + buf * KBUF);
        unsigned vbase = (unsigned)__cvta_generic_to_shared(Vs + buf * VBUF);
        #pragma unroll
        for (int p = 0; p < 4; p++) {
            int idx = tid + p * 256;
            int row = idx >> 4, c4 = (idx & 15) * 4;
            const float* rp = qkv + (base + kt * 64 + row) * QKV_N;
            CP_ASYNC16(kbase + (row * FSK + c4) * 4, rp + koff + c4);
            CP_ASYNC16(vbase + (row * FSV + c4) * 4, rp + voff + c4);
        }
    };

    float l[2] = {0.f, 0.f};
    float c[4][2][4] = {};

    const int NT = SEQ / 64;
    loadKV(0, 0);
    asm volatile("cp.async.commit_group;\n");

    for (int kt = 0; kt < NT; kt++) {
        if (kt + 1 < NT) {
            __syncthreads();
            loadKV((kt + 1) & 1, kt + 1);
            asm volatile("cp.async.commit_group;\n");
            asm volatile("cp.async.wait_group 1;\n");
        } else {
            asm volatile("cp.async.wait_group 0;\n");
        }
        __syncthreads();

        const float* Kb = Ks + (kt & 1) * KBUF;
        const float* Vb = Vs + (kt & 1) * VBUF;

        float sc[8][4] = {};
        #pragma unroll
        for (int ks = 0; ks < 8; ks++) {
            const int kk = ks * 8;
            #pragma unroll
            for (int nt = 0; nt < 8; nt++) {
                float2 bb = *(const float2*)&Kb[(nt * 8 + g) * FSK + kk + 2 * tg];
                mma_tf32(sc[nt][0], sc[nt][1], sc[nt][2], sc[nt][3],
                         qf[ks][0], qf[ks][1], qf[ks][2], qf[ks][3],
                         __float_as_uint(bb.x), __float_as_uint(bb.y));
            }
        }

        #pragma unroll
        for (int rh = 0; rh < 2; rh++) {
            float rs = 0.f;
            int prow = (qr + g + 8 * rh) * FSP;
            #pragma unroll
            for (int nt = 0; nt < 8; nt++) {
                float p0 = __uint_as_float(f2tf(fex2(sc[nt][2 * rh])));
                float p1 = __uint_as_float(f2tf(fex2(sc[nt][2 * rh + 1])));
                rs += p0 + p1;
                *(float2*)(Ps + prow + nt * 8 + 2 * tg) = make_float2(p0, p1);
            }
            rs += __shfl_xor_sync(0xffffffffu, rs, 1);
            rs += __shfl_xor_sync(0xffffffffu, rs, 2);
            l[rh] += rs;
        }
        __syncwarp();

        #pragma unroll
        for (int ks = 0; ks < 8; ks++) {
            const int kk = ks * 8;
            unsigned pb[2][2];
            #pragma unroll
            for (int nh = 0; nh < 2; nh++) {
                pb[nh][0] = __float_as_uint(Ps[(qr + nh * 8 + g) * FSP + kk + tg]);
                pb[nh][1] = __float_as_uint(Ps[(qr + nh * 8 + g) * FSP + kk + tg + 4]);
            }
            #pragma unroll
            for (int mt = 0; mt < 4; mt++) {
                float2 va0 = *(const float2*)&Vb[(kk + tg)     * FSV + mt * 16 + 2 * g];
                float2 va1 = *(const float2*)&Vb[(kk + tg + 4) * FSV + mt * 16 + 2 * g];
                #pragma unroll
                for (int nh = 0; nh < 2; nh++)
                    mma_tf32(c[mt][nh][0], c[mt][nh][1], c[mt][nh][2], c[mt][nh][3],
                             __float_as_uint(va0.x), __float_as_uint(va0.y),
                             __float_as_uint(va1.x), __float_as_uint(va1.y),
                             pb[nh][0], pb[nh][1]);
            }
        }
        __syncwarp();
    }

    float linv[2][2];
    #pragma unroll
    for (int nh = 0; nh < 2; nh++) {
        linv[nh][0] = 1.f / __shfl_sync(0xffffffffu, l[nh], 8 * tg);
        linv[nh][1] = 1.f / __shfl_sync(0xffffffffu, l[nh], 8 * tg + 4);
    }
    const int gp = ((g & 3) << 1) | ((g >> 2) & 1);   // perm8 within-8 offset
    #pragma unroll
    for (int mt = 0; mt < 4; mt++) {
        #pragma unroll
        for (int nh = 0; nh < 2; nh++) {
            int q = qt * 128 + qr + nh * 8 + 2 * tg;
            int d0 = mt * 16 + gp;                    // perm8'd column
            size_t ro = (base + q) * (size_t)DIMN + h * DHEAD;
            attn[ro + d0]            = __uint_as_float(f2tf(c[mt][nh][0] * linv[nh][0]));
            attn[ro + DIMN + d0]     = __uint_as_float(f2tf(c[mt][nh][1] * linv[nh][1]));
            attn[ro + d0 + 8]        = __uint_as_float(f2tf(c[mt][nh][2] * linv[nh][0]));
            attn[ro + DIMN + d0 + 8] = __uint_as_float(f2tf(c[mt][nh][3] * linv[nh][1]));
        }
    }
}

// ---------------------------------------------------------------------------
extern "C" void kernel_launch(void* const* d_in, const int* in_sizes, int n_in,
                              void* d_out, int out_size)
{
    const float* x      = (const float*)d_in[0];
    const float* gamma  = (const float*)d_in[1];
    const float* beta   = (const float*)d_in[2];
    const float* w_qkv  = (const float*)d_in[3];
    const float* w_out  = (const float*)d_in[4];
    const float* b_out  = (const float*)d_in[5];
    float* out = (float*)d_out;

    float *xn, *qkvp, *attnp, *wq, *wo;
    cudaGetSymbolAddress((void**)&xn,    g_xn);
    cudaGetSymbolAddress((void**)&qkvp,  g_qkv);
    cudaGetSymbolAddress((void**)&attnp, g_attn);
    cudaGetSymbolAddress((void**)&wq,    g_wq);
    cudaGetSymbolAddress((void**)&wo,    g_wo);

    const int gemm_smem  = 4 * GBUF * sizeof(float);    // 81920
    const int flash_smem = FL_SMF * sizeof(float);      // 108544
    cudaFuncSetAttribute(gemm_tc,   cudaFuncAttributeMaxDynamicSharedMemorySize, gemm_smem);
    cudaFuncSetAttribute(flash_tc4, cudaFuncAttributeMaxDynamicSharedMemorySize, flash_smem);

    tpose_cvt<<<dim3(DIMN / 32, QKV_N / 32), 256>>>(w_qkv, wq, DIMN, QKV_N);
    tpose_cvt<<<dim3(DIMN / 32, DIMN  / 32), 256>>>(w_out, wo, DIMN, DIMN);
    ln_kernel<<<ROWS, 256>>>(x, gamma, beta);
    gemm_tc<<<dim3(QKV_N / 128, ROWS / 128), 256, gemm_smem>>>(xn, wq, nullptr, qkvp,
                                                               ROWS, QKV_N, DIMN, 1);
    flash_tc4<<<dim3(SEQ / 128, BATCH * HEADS), 256, flash_smem>>>(qkvp, attnp);
    gemm_tc<<<dim3(DIMN / 128, ROWS / 128), 256, gemm_smem>>>(attnp, wo, b_out, out,
                                                              ROWS, DIMN, DIMN, 0);
}

// round 9
// speedup vs baseline: 1.0456x; 1.0456x over previous
#include <cuda_runtime.h>
#include <math.h>

#define BATCH 4
#define SEQ   2048
#define DIMN  1024
#define HEADS 16
#define DHEAD 64
#define ROWS  (BATCH*SEQ)      /* 8192 */
#define QKV_N (3*DIMN)         /* 3072 */

// Scratch (allocation-free rule: __device__ globals)
static __device__ float g_xn[(size_t)ROWS*DIMN];
static __device__ float g_qkv[(size_t)ROWS*QKV_N];   // K cols perm8'd, V cols perm16'd
static __device__ float g_attn[(size_t)ROWS*DIMN];
static __device__ float g_wq[(size_t)DIMN*QKV_N];
static __device__ float g_wo[(size_t)DIMN*DIMN];

// ---------------------------------------------------------------------------
__device__ __forceinline__ unsigned f2tf(float x) {
    unsigned r;
    asm("cvt.rna.tf32.f32 %0, %1;" : "=r"(r) : "f"(x));
    return r;
}

__device__ __forceinline__ float fex2(float x) {   // 2^x, clamped below
    float r;
    x = fmaxf(x, -126.f);
    asm("ex2.approx.ftz.f32 %0, %1;" : "=f"(r) : "f"(x));
    return r;
}

// qkv column permutation applied by gemm1 epilogue:
//  K region (1024..2047): within-8 (d,d+4)->(2d',2d'+1)
//  V region (2048..3071): within-16 (d,d+8)->(2d',2d'+1)
__device__ __forceinline__ int permcol(int c) {
    int reg = c >> 10;
    if (reg == 1) return (c & ~7)  | ((c & 3) << 1) | ((c >> 2) & 1);
    if (reg == 2) return (c & ~15) | ((c & 7) << 1) | ((c >> 3) & 1);
    return c;
}

__device__ __forceinline__ void mma_tf32(float& c0, float& c1, float& c2, float& c3,
                                         unsigned a0, unsigned a1, unsigned a2, unsigned a3,
                                         unsigned b0, unsigned b1) {
    asm volatile(
        "mma.sync.aligned.m16n8k8.row.col.f32.tf32.tf32.f32 "
        "{%0,%1,%2,%3}, {%4,%5,%6,%7}, {%8,%9}, {%0,%1,%2,%3};\n"
        : "+f"(c0), "+f"(c1), "+f"(c2), "+f"(c3)
        : "r"(a0), "r"(a1), "r"(a2), "r"(a3), "r"(b0), "r"(b1));
}

#define CP_ASYNC16(dst, src) \
    asm volatile("cp.async.cg.shared.global [%0], [%1], 16;\n" :: "r"(dst), "l"(src))

// ---------------------------------------------------------------------------
__global__ __launch_bounds__(256) void cvt_kernel(const float* __restrict__ src,
                                                  float* __restrict__ dst, int n4) {
    int i = blockIdx.x * 256 + threadIdx.x;
    if (i < n4) {
        float4 v = ((const float4*)src)[i];
        uint4 o;
        o.x = f2tf(v.x); o.y = f2tf(v.y); o.z = f2tf(v.z); o.w = f2tf(v.w);
        ((uint4*)dst)[i] = o;
    }
}

// ---------------------------------------------------------------------------
__global__ __launch_bounds__(256) void ln_kernel(const float* __restrict__ x,
                                                 const float* __restrict__ gamma,
                                                 const float* __restrict__ beta) {
    __shared__ float red[16];
    const int row = blockIdx.x;
    const int t = threadIdx.x;
    const float* xr = x + (size_t)row * DIMN;
    float4 v = *(const float4*)(xr + t * 4);
    float s = v.x + v.y + v.z + v.w;
    float q = v.x*v.x + v.y*v.y + v.z*v.z + v.w*v.w;
    #pragma unroll
    for (int o = 16; o; o >>= 1) {
        s += __shfl_xor_sync(0xffffffffu, s, o);
        q += __shfl_xor_sync(0xffffffffu, q, o);
    }
    if ((t & 31) == 0) { red[t >> 5] = s; red[8 + (t >> 5)] = q; }
    __syncthreads();
    if (t < 32) {
        float ss = (t < 8) ? red[t] : 0.f;
        float qq = (t < 8) ? red[8 + t] : 0.f;
        #pragma unroll
        for (int o = 4; o; o >>= 1) {
            ss += __shfl_xor_sync(0xffffffffu, ss, o);
            qq += __shfl_xor_sync(0xffffffffu, qq, o);
        }
        if (t == 0) { red[0] = ss; red[1] = qq; }
    }
    __syncthreads();
    const float mean = red[0] * (1.f / DIMN);
    const float var  = red[1] * (1.f / DIMN) - mean * mean;
    const float inv  = rsqrtf(var + 1e-5f);
    float4 g = *(const float4*)(gamma + t * 4);
    float4 b = *(const float4*)(beta  + t * 4);
    uint4 o4;
    o4.x = f2tf((v.x - mean) * inv * g.x + b.x);
    o4.y = f2tf((v.y - mean) * inv * g.y + b.y);
    o4.z = f2tf((v.z - mean) * inv * g.z + b.z);
    o4.w = f2tf((v.w - mean) * inv * g.w + b.w);
    *(uint4*)(g_xn + (size_t)row * DIMN + t * 4) = o4;
}

// ---------------------------------------------------------------------------
// tf32 tensor-core GEMM (R7 fragment paths), 3-stage cp.async pipeline with
// ONE barrier per K-tile. mode 0: fp32 out +bias. mode 1: tf32 out, qkv perm.
// ---------------------------------------------------------------------------
#define ASTR 36
#define BSTR 136
#define ABUF (128*ASTR)                 /* 4608 floats */
#define BBUF (32*BSTR)                  /* 4352 floats */
#define STG  (ABUF+BBUF)                /* 8960 floats per stage */

__global__ __launch_bounds__(256) void gemm_tc(const float* __restrict__ A,
                                               const float* __restrict__ B,
                                               const float* __restrict__ bias,
                                               float* __restrict__ C,
                                               int M, int N, int K, int mode) {
    extern __shared__ float sm[];

    const int tid = threadIdx.x;
    const int wid = tid >> 5, lane = tid & 31;
    const int g = lane >> 2, tg = lane & 3;
    const int wm = wid >> 1, wn = wid & 1;
    const int bm = blockIdx.y * 128, bn = blockIdx.x * 128;

    float c[2][8][4] = {};

    auto loadAB = [&](int buf, int k0) {
        float* As = sm + buf * STG;
        float* Bs = As + ABUF;
        unsigned abase = (unsigned)__cvta_generic_to_shared(As);
        unsigned bbase = (unsigned)__cvta_generic_to_shared(Bs);
        #pragma unroll
        for (int p = 0; p < 4; p++) {
            int idx = tid + p * 256;
            int ar = idx >> 3, ac = (idx & 7) * 4;
            CP_ASYNC16(abase + (ar * ASTR + ac) * 4, A + (size_t)(bm + ar) * K + k0 + ac);
            int br = idx >> 5, bc = (idx & 31) * 4;
            CP_ASYNC16(bbase + (br * BSTR + bc) * 4, B + (size_t)(k0 + br) * N + bn + bc);
        }
    };

    const int nk = K / 32;                      // >= 2 always here
    loadAB(0, 0);
    asm volatile("cp.async.commit_group;\n");
    loadAB(1, 32);
    asm volatile("cp.async.commit_group;\n");

    int cur = 0, nxt = 2;                       // kb%3 and (kb+2)%3
    for (int kb = 0; kb < nk; kb++) {
        if (kb + 1 < nk) {
            asm volatile("cp.async.wait_group 1;\n");
        } else {
            asm volatile("cp.async.wait_group 0;\n");
        }
        __syncthreads();                        // single barrier per tile
        if (kb + 2 < nk) {
            loadAB(nxt, (kb + 2) * 32);
            asm volatile("cp.async.commit_group;\n");
        }

        const float* Ab = sm + cur * STG;
        const float* Bb = Ab + ABUF;
        #pragma unroll
        for (int ks = 0; ks < 4; ks++) {
            const int kk = ks * 8;
            unsigned a[2][4], b[8][2];
            #pragma unroll
            for (int mt = 0; mt < 2; mt++) {
                int r0 = wm * 32 + mt * 16;
                a[mt][0] = __float_as_uint(Ab[(r0 + g)     * ASTR + kk + tg]);
                a[mt][1] = __float_as_uint(Ab[(r0 + g + 8) * ASTR + kk + tg]);
                a[mt][2] = __float_as_uint(Ab[(r0 + g)     * ASTR + kk + tg + 4]);
                a[mt][3] = __float_as_uint(Ab[(r0 + g + 8) * ASTR + kk + tg + 4]);
            }
            #pragma unroll
            for (int nt = 0; nt < 8; nt++) {
                int col = wn * 64 + nt * 8 + g;
                b[nt][0] = __float_as_uint(Bb[(kk + tg)     * BSTR + col]);
                b[nt][1] = __float_as_uint(Bb[(kk + tg + 4) * BSTR + col]);
            }
            #pragma unroll
            for (int mt = 0; mt < 2; mt++)
                #pragma unroll
                for (int nt = 0; nt < 8; nt++)
                    mma_tf32(c[mt][nt][0], c[mt][nt][1], c[mt][nt][2], c[mt][nt][3],
                             a[mt][0], a[mt][1], a[mt][2], a[mt][3],
                             b[nt][0], b[nt][1]);
        }
        cur = (cur == 2) ? 0 : cur + 1;
        nxt = (nxt == 2) ? 0 : nxt + 1;
    }

    #pragma unroll
    for (int mt = 0; mt < 2; mt++) {
        int r0 = bm + wm * 32 + mt * 16 + g;
        #pragma unroll
        for (int nt = 0; nt < 8; nt++) {
            int col = bn + wn * 64 + nt * 8 + 2 * tg;
            if (mode == 0) {
                float b0 = bias ? bias[col] : 0.f, b1 = bias ? bias[col + 1] : 0.f;
                *(float2*)(C + (size_t)r0 * N + col) =
                    make_float2(c[mt][nt][0] + b0, c[mt][nt][1] + b1);
                *(float2*)(C + (size_t)(r0 + 8) * N + col) =
                    make_float2(c[mt][nt][2] + b0, c[mt][nt][3] + b1);
            } else {
                int c0 = permcol(col), c1 = permcol(col + 1);
                C[(size_t)r0 * N + c0]       = __uint_as_float(f2tf(c[mt][nt][0]));
                C[(size_t)r0 * N + c1]       = __uint_as_float(f2tf(c[mt][nt][1]));
                C[(size_t)(r0 + 8) * N + c0] = __uint_as_float(f2tf(c[mt][nt][2]));
                C[(size_t)(r0 + 8) * N + c1] = __uint_as_float(f2tf(c[mt][nt][3]));
            }
        }
    }
}

// ---------------------------------------------------------------------------
// Flash attention v5: R7 data paths, but ONE barrier per KV tile
// (loads issued after the barrier; compute phase hides them).
// ---------------------------------------------------------------------------
#define FSK 72
#define FSV 72
#define FSP 68
#define KBUF (64*FSK)
#define VBUF (64*FSV)
#define FL_SMF (2*KBUF + 2*VBUF + 128*FSP)    /* 27136 floats = 108544 B */

__global__ __launch_bounds__(256, 2) void flash_tc5(const float* __restrict__ qkv,
                                                    float* __restrict__ attn) {
    extern __shared__ float sm[];
    float* Ks = sm;                        // [2][64][FSK], perm8 cols
    float* Vs = sm + 2 * KBUF;             // [2][64][FSV], perm16 cols
    float* Ps = sm + 2 * KBUF + 2 * VBUF;  // [128][FSP]; doubles as Q stage

    const int tid = threadIdx.x;
    const int wid = tid >> 5, lane = tid & 31;
    const int g = lane >> 2, tg = lane & 3;
    const int qr = wid * 16;
    const int qt = blockIdx.x;
    const int bh = blockIdx.y;
    const int b = bh >> 4, h = bh & 15;
    const size_t base = (size_t)b * SEQ;
    const int qoff = h * DHEAD;
    const int koff = DIMN + h * DHEAD;
    const int voff = 2 * DIMN + h * DHEAD;

    // ---- stage Q, pull A-fragments into registers ----
    #pragma unroll
    for (int p = 0; p < 8; p++) {
        int idx = tid + p * 256;
        int row = idx >> 4, c4 = (idx & 15) * 4;
        *(float4*)(Ps + row * FSP + c4) =
            *(const float4*)(qkv + (base + qt * 128 + row) * QKV_N + qoff + c4);
    }
    __syncthreads();
    unsigned qf[8][4];
    {
        const float QS = 0.125f * 1.4426950408889634f;
        const int r0 = (qr + g) * FSP, r1 = (qr + g + 8) * FSP;
        #pragma unroll
        for (int ks = 0; ks < 8; ks++) {
            int c = ks * 8 + tg;
            qf[ks][0] = f2tf(Ps[r0 + c]     * QS);
            qf[ks][1] = f2tf(Ps[r1 + c]     * QS);
            qf[ks][2] = f2tf(Ps[r0 + c + 4] * QS);
            qf[ks][3] = f2tf(Ps[r1 + c + 4] * QS);
        }
    }

    auto loadKV = [&](int buf, int kt) {
        unsigned kbase = (unsigned)__cvta_generic_to_shared(Ks + buf * KBUF);
        unsigned vbase = (unsigned)__cvta_generic_to_shared(Vs + buf * VBUF);
        #pragma unroll
        for (int p = 0; p < 4; p++) {
            int idx = tid + p * 256;
            int row = idx >> 4, c4 = (idx & 15) * 4;
            const float* rp = qkv + (base + kt * 64 + row) * QKV_N;
            CP_ASYNC16(kbase + (row * FSK + c4) * 4, rp + koff + c4);
            CP_ASYNC16(vbase + (row * FSV + c4) * 4, rp + voff + c4);
        }
    };

    float l[2] = {0.f, 0.f};
    float c[4][2][4] = {};

    const int NT = SEQ / 64;
    loadKV(0, 0);
    asm volatile("cp.async.commit_group;\n");

    for (int kt = 0; kt < NT; kt++) {
        asm volatile("cp.async.wait_group 0;\n");
        __syncthreads();                      // single barrier per tile
        if (kt + 1 < NT) {
            loadKV((kt + 1) & 1, kt + 1);     // writes buffer consumed at kt-1
            asm volatile("cp.async.commit_group;\n");
        }

        const float* Kb = Ks + (kt & 1) * KBUF;
        const float* Vb = Vs + (kt & 1) * VBUF;

        // ---- S = Q @ K^T : B via LDS.64 (perm8 layout) ----
        float sc[8][4] = {};
        #pragma unroll
        for (int ks = 0; ks < 8; ks++) {
            const int kk = ks * 8;
            #pragma unroll
            for (int nt = 0; nt < 8; nt++) {
                float2 bb = *(const float2*)&Kb[(nt * 8 + g) * FSK + kk + 2 * tg];
                mma_tf32(sc[nt][0], sc[nt][1], sc[nt][2], sc[nt][3],
                         qf[ks][0], qf[ks][1], qf[ks][2], qf[ks][3],
                         __float_as_uint(bb.x), __float_as_uint(bb.y));
            }
        }

        // ---- softmax (no max-subtraction; exact identity), MUFU ex2 ----
        #pragma unroll
        for (int rh = 0; rh < 2; rh++) {
            float rs = 0.f;
            int prow = (qr + g + 8 * rh) * FSP;
            #pragma unroll
            for (int nt = 0; nt < 8; nt++) {
                float p0 = __uint_as_float(f2tf(fex2(sc[nt][2 * rh])));
                float p1 = __uint_as_float(f2tf(fex2(sc[nt][2 * rh + 1])));
                rs += p0 + p1;
                *(float2*)(Ps + prow + nt * 8 + 2 * tg) = make_float2(p0, p1);
            }
            rs += __shfl_xor_sync(0xffffffffu, rs, 1);
            rs += __shfl_xor_sync(0xffffffffu, rs, 2);
            l[rh] += rs;
        }
        __syncwarp();

        // ---- O^T += V^T @ P^T : A (V) via LDS.64 (perm16), B (P) scalar ----
        #pragma unroll
        for (int ks = 0; ks < 8; ks++) {
            const int kk = ks * 8;
            unsigned pb[2][2];
            #pragma unroll
            for (int nh = 0; nh < 2; nh++) {
                pb[nh][0] = __float_as_uint(Ps[(qr + nh * 8 + g) * FSP + kk + tg]);
                pb[nh][1] = __float_as_uint(Ps[(qr + nh * 8 + g) * FSP + kk + tg + 4]);
            }
            #pragma unroll
            for (int mt = 0; mt < 4; mt++) {
                float2 va0 = *(const float2*)&Vb[(kk + tg)     * FSV + mt * 16 + 2 * g];
                float2 va1 = *(const float2*)&Vb[(kk + tg + 4) * FSV + mt * 16 + 2 * g];
                #pragma unroll
                for (int nh = 0; nh < 2; nh++)
                    mma_tf32(c[mt][nh][0], c[mt][nh][1], c[mt][nh][2], c[mt][nh][3],
                             __float_as_uint(va0.x), __float_as_uint(va0.y),
                             __float_as_uint(va1.x), __float_as_uint(va1.y),
                             pb[nh][0], pb[nh][1]);
            }
        }
        __syncwarp();   // P reads done before next tile's softmax overwrites
    }

    // ---- epilogue ----
    float linv[2][2];
    #pragma unroll
    for (int nh = 0; nh < 2; nh++) {
        linv[nh][0] = 1.f / __shfl_sync(0xffffffffu, l[nh], 8 * tg);
        linv[nh][1] = 1.f / __shfl_sync(0xffffffffu, l[nh], 8 * tg + 4);
    }
    #pragma unroll
    for (int mt = 0; mt < 4; mt++) {
        #pragma unroll
        for (int nh = 0; nh < 2; nh++) {
            int q = qt * 128 + qr + nh * 8 + 2 * tg;
            int d0 = mt * 16 + g;
            size_t ro = (base + q) * (size_t)DIMN + h * DHEAD;
            attn[ro + d0]            = __uint_as_float(f2tf(c[mt][nh][0] * linv[nh][0]));
            attn[ro + DIMN + d0]     = __uint_as_float(f2tf(c[mt][nh][1] * linv[nh][1]));
            attn[ro + d0 + 8]        = __uint_as_float(f2tf(c[mt][nh][2] * linv[nh][0]));
            attn[ro + DIMN + d0 + 8] = __uint_as_float(f2tf(c[mt][nh][3] * linv[nh][1]));
        }
    }
}

// ---------------------------------------------------------------------------
extern "C" void kernel_launch(void* const* d_in, const int* in_sizes, int n_in,
                              void* d_out, int out_size)
{
    const float* x      = (const float*)d_in[0];
    const float* gamma  = (const float*)d_in[1];
    const float* beta   = (const float*)d_in[2];
    const float* w_qkv  = (const float*)d_in[3];
    const float* w_out  = (const float*)d_in[4];
    const float* b_out  = (const float*)d_in[5];
    float* out = (float*)d_out;

    float *xn, *qkvp, *attnp, *wq, *wo;
    cudaGetSymbolAddress((void**)&xn,    g_xn);
    cudaGetSymbolAddress((void**)&qkvp,  g_qkv);
    cudaGetSymbolAddress((void**)&attnp, g_attn);
    cudaGetSymbolAddress((void**)&wq,    g_wq);
    cudaGetSymbolAddress((void**)&wo,    g_wo);

    const int gemm_smem  = 3 * STG * sizeof(float);     // 107520
    const int flash_smem = FL_SMF * sizeof(float);      // 108544
    cudaFuncSetAttribute(gemm_tc,   cudaFuncAttributeMaxDynamicSharedMemorySize, gemm_smem);
    cudaFuncSetAttribute(flash_tc5, cudaFuncAttributeMaxDynamicSharedMemorySize, flash_smem);

    cvt_kernel<<<(DIMN * QKV_N / 4 + 255) / 256, 256>>>(w_qkv, wq, DIMN * QKV_N / 4);
    cvt_kernel<<<(DIMN * DIMN  / 4 + 255) / 256, 256>>>(w_out, wo, DIMN * DIMN / 4);
    ln_kernel<<<ROWS, 256>>>(x, gamma, beta);
    gemm_tc<<<dim3(QKV_N / 128, ROWS / 128), 256, gemm_smem>>>(xn, wq, nullptr, qkvp,
                                                               ROWS, QKV_N, DIMN, 1);
    flash_tc5<<<dim3(SEQ / 128, BATCH * HEADS), 256, flash_smem>>>(qkvp, attnp);
    gemm_tc<<<dim3(DIMN / 128, ROWS / 128), 256, gemm_smem>>>(attnp, wo, b_out, out,
                                                              ROWS, DIMN, DIMN, 0);
}

// round 12
// speedup vs baseline: 1.0530x; 1.0071x over previous
#include <cuda_runtime.h>
#include <math.h>

#define BATCH 4
#define SEQ   2048
#define DIMN  1024
#define HEADS 16
#define DHEAD 64
#define ROWS  (BATCH*SEQ)      /* 8192 */
#define QKV_N (3*DIMN)         /* 3072 */

// Scratch (allocation-free rule: __device__ globals)
static __device__ float g_xn[(size_t)ROWS*DIMN];
static __device__ float g_qkv[(size_t)ROWS*QKV_N];   // K cols perm8'd, V cols perm16'd
static __device__ float g_attn[(size_t)ROWS*DIMN];
static __device__ float g_wq[(size_t)DIMN*QKV_N];
static __device__ float g_wo[(size_t)DIMN*DIMN];

// ---------------------------------------------------------------------------
__device__ __forceinline__ unsigned f2tf(float x) {
    unsigned r;
    asm("cvt.rna.tf32.f32 %0, %1;" : "=r"(r) : "f"(x));
    return r;
}

__device__ __forceinline__ float fex2(float x) {   // 2^x, clamped below
    float r;
    x = fmaxf(x, -126.f);
    asm("ex2.approx.ftz.f32 %0, %1;" : "=f"(r) : "f"(x));
    return r;
}

// qkv column permutation applied by gemm1 epilogue:
//  K region (1024..2047): within-8 (d,d+4)->(2d',2d'+1)
//  V region (2048..3071): within-16 (d,d+8)->(2d',2d'+1)
__device__ __forceinline__ int permcol(int c) {
    int reg = c >> 10;
    if (reg == 1) return (c & ~7)  | ((c & 3) << 1) | ((c >> 2) & 1);
    if (reg == 2) return (c & ~15) | ((c & 7) << 1) | ((c >> 3) & 1);
    return c;
}

__device__ __forceinline__ void mma_tf32(float& c0, float& c1, float& c2, float& c3,
                                         unsigned a0, unsigned a1, unsigned a2, unsigned a3,
                                         unsigned b0, unsigned b1) {
    asm volatile(
        "mma.sync.aligned.m16n8k8.row.col.f32.tf32.tf32.f32 "
        "{%0,%1,%2,%3}, {%4,%5,%6,%7}, {%8,%9}, {%0,%1,%2,%3};\n"
        : "+f"(c0), "+f"(c1), "+f"(c2), "+f"(c3)
        : "r"(a0), "r"(a1), "r"(a2), "r"(a3), "r"(b0), "r"(b1));
}

#define CP_ASYNC16(dst, src) \
    asm volatile("cp.async.cg.shared.global [%0], [%1], 16;\n" :: "r"(dst), "l"(src))

// ---------------------------------------------------------------------------
// prep: wq cvt (blocks 0..3071), wo cvt (3072..4095), ln (4096..12287)
// ---------------------------------------------------------------------------
#define PREP_WQ_BLKS 3072
#define PREP_WO_BLKS 1024
#define PREP_BLKS    (PREP_WQ_BLKS + PREP_WO_BLKS + ROWS)

__global__ __launch_bounds__(256) void prep_kernel(const float* __restrict__ w_qkv,
                                                   const float* __restrict__ w_out,
                                                   const float* __restrict__ x,
                                                   const float* __restrict__ gamma,
                                                   const float* __restrict__ beta) {
    cudaTriggerProgrammaticLaunchCompletion();
    const int blk = blockIdx.x;
    const int t = threadIdx.x;

    if (blk < PREP_WQ_BLKS + PREP_WO_BLKS) {
        const float* src = (blk < PREP_WQ_BLKS) ? w_qkv : w_out;
        float* dst       = (blk < PREP_WQ_BLKS) ? g_wq  : g_wo;
        int i = (blk < PREP_WQ_BLKS ? blk : blk - PREP_WQ_BLKS) * 256 + t;
        float4 v = ((const float4*)src)[i];
        uint4 o;
        o.x = f2tf(v.x); o.y = f2tf(v.y); o.z = f2tf(v.z); o.w = f2tf(v.w);
        ((uint4*)dst)[i] = o;
        return;
    }

    // LayerNorm row
    __shared__ float red[16];
    const int row = blk - (PREP_WQ_BLKS + PREP_WO_BLKS);
    const float* xr = x + (size_t)row * DIMN;
    float4 v = *(const float4*)(xr + t * 4);
    float s = v.x + v.y + v.z + v.w;
    float q = v.x*v.x + v.y*v.y + v.z*v.z + v.w*v.w;
    #pragma unroll
    for (int o = 16; o; o >>= 1) {
        s += __shfl_xor_sync(0xffffffffu, s, o);
        q += __shfl_xor_sync(0xffffffffu, q, o);
    }
    if ((t & 31) == 0) { red[t >> 5] = s; red[8 + (t >> 5)] = q; }
    __syncthreads();
    if (t < 32) {
        float ss = (t < 8) ? red[t] : 0.f;
        float qq = (t < 8) ? red[8 + t] : 0.f;
        #pragma unroll
        for (int o = 4; o; o >>= 1) {
            ss += __shfl_xor_sync(0xffffffffu, ss, o);
            qq += __shfl_xor_sync(0xffffffffu, qq, o);
        }
        if (t == 0) { red[0] = ss; red[1] = qq; }
    }
    __syncthreads();
    const float mean = red[0] * (1.f / DIMN);
    const float var  = red[1] * (1.f / DIMN) - mean * mean;
    const float inv  = rsqrtf(var + 1e-5f);
    float4 g = *(const float4*)(gamma + t * 4);
    float4 b = *(const float4*)(beta  + t * 4);
    uint4 o4;
    o4.x = f2tf((v.x - mean) * inv * g.x + b.x);
    o4.y = f2tf((v.y - mean) * inv * g.y + b.y);
    o4.z = f2tf((v.z - mean) * inv * g.z + b.z);
    o4.w = f2tf((v.w - mean) * inv * g.w + b.w);
    *(uint4*)(g_xn + (size_t)row * DIMN + t * 4) = o4;
}

// ---------------------------------------------------------------------------
// tf32 tensor-core GEMM (R9): 3-stage cp.async pipeline, ONE barrier per
// K-tile. mode 0: fp32 out +bias. mode 1: tf32 out, qkv column perm.
// PDL: waits for producer grid before first gmem read; triggers consumer.
// ---------------------------------------------------------------------------
#define ASTR 36
#define BSTR 136
#define ABUF (128*ASTR)                 /* 4608 floats */
#define BBUF (32*BSTR)                  /* 4352 floats */
#define STG  (ABUF+BBUF)                /* 8960 floats per stage */

__global__ __launch_bounds__(256) void gemm_tc(const float* __restrict__ A,
                                               const float* __restrict__ B,
                                               const float* __restrict__ bias,
                                               float* __restrict__ C,
                                               int M, int N, int K, int mode) {
    extern __shared__ float sm[];

    cudaGridDependencySynchronize();
    cudaTriggerProgrammaticLaunchCompletion();

    const int tid = threadIdx.x;
    const int wid = tid >> 5, lane = tid & 31;
    const int g = lane >> 2, tg = lane & 3;
    const int wm = wid >> 1, wn = wid & 1;
    const int bm = blockIdx.y * 128, bn = blockIdx.x * 128;

    float c[2][8][4] = {};

    auto loadAB = [&](int buf, int k0) {
        float* As = sm + buf * STG;
        float* Bs = As + ABUF;
        unsigned abase = (unsigned)__cvta_generic_to_shared(As);
        unsigned bbase = (unsigned)__cvta_generic_to_shared(Bs);
        #pragma unroll
        for (int p = 0; p < 4; p++) {
            int idx = tid + p * 256;
            int ar = idx >> 3, ac = (idx & 7) * 4;
            CP_ASYNC16(abase + (ar * ASTR + ac) * 4, A + (size_t)(bm + ar) * K + k0 + ac);
            int br = idx >> 5, bc = (idx & 31) * 4;
            CP_ASYNC16(bbase + (br * BSTR + bc) * 4, B + (size_t)(k0 + br) * N + bn + bc);
        }
    };

    const int nk = K / 32;
    loadAB(0, 0);
    asm volatile("cp.async.commit_group;\n");
    loadAB(1, 32);
    asm volatile("cp.async.commit_group;\n");

    int cur = 0, nxt = 2;
    for (int kb = 0; kb < nk; kb++) {
        if (kb + 1 < nk) {
            asm volatile("cp.async.wait_group 1;\n");
        } else {
            asm volatile("cp.async.wait_group 0;\n");
        }
        __syncthreads();
        if (kb + 2 < nk) {
            loadAB(nxt, (kb + 2) * 32);
            asm volatile("cp.async.commit_group;\n");
        }

        const float* Ab = sm + cur * STG;
        const float* Bb = Ab + ABUF;
        #pragma unroll
        for (int ks = 0; ks < 4; ks++) {
            const int kk = ks * 8;
            unsigned a[2][4], b[8][2];
            #pragma unroll
            for (int mt = 0; mt < 2; mt++) {
                int r0 = wm * 32 + mt * 16;
                a[mt][0] = __float_as_uint(Ab[(r0 + g)     * ASTR + kk + tg]);
                a[mt][1] = __float_as_uint(Ab[(r0 + g + 8) * ASTR + kk + tg]);
                a[mt][2] = __float_as_uint(Ab[(r0 + g)     * ASTR + kk + tg + 4]);
                a[mt][3] = __float_as_uint(Ab[(r0 + g + 8) * ASTR + kk + tg + 4]);
            }
            #pragma unroll
            for (int nt = 0; nt < 8; nt++) {
                int col = wn * 64 + nt * 8 + g;
                b[nt][0] = __float_as_uint(Bb[(kk + tg)     * BSTR + col]);
                b[nt][1] = __float_as_uint(Bb[(kk + tg + 4) * BSTR + col]);
            }
            #pragma unroll
            for (int mt = 0; mt < 2; mt++)
                #pragma unroll
                for (int nt = 0; nt < 8; nt++)
                    mma_tf32(c[mt][nt][0], c[mt][nt][1], c[mt][nt][2], c[mt][nt][3],
                             a[mt][0], a[mt][1], a[mt][2], a[mt][3],
                             b[nt][0], b[nt][1]);
        }
        cur = (cur == 2) ? 0 : cur + 1;
        nxt = (nxt == 2) ? 0 : nxt + 1;
    }

    #pragma unroll
    for (int mt = 0; mt < 2; mt++) {
        int r0 = bm + wm * 32 + mt * 16 + g;
        #pragma unroll
        for (int nt = 0; nt < 8; nt++) {
            int col = bn + wn * 64 + nt * 8 + 2 * tg;
            if (mode == 0) {
                float b0 = bias ? bias[col] : 0.f, b1 = bias ? bias[col + 1] : 0.f;
                *(float2*)(C + (size_t)r0 * N + col) =
                    make_float2(c[mt][nt][0] + b0, c[mt][nt][1] + b1);
                *(float2*)(C + (size_t)(r0 + 8) * N + col) =
                    make_float2(c[mt][nt][2] + b0, c[mt][nt][3] + b1);
            } else {
                int c0 = permcol(col), c1 = permcol(col + 1);
                C[(size_t)r0 * N + c0]       = __uint_as_float(f2tf(c[mt][nt][0]));
                C[(size_t)r0 * N + c1]       = __uint_as_float(f2tf(c[mt][nt][1]));
                C[(size_t)(r0 + 8) * N + c0] = __uint_as_float(f2tf(c[mt][nt][2]));
                C[(size_t)(r0 + 8) * N + c1] = __uint_as_float(f2tf(c[mt][nt][3]));
            }
        }
    }
}

// ---------------------------------------------------------------------------
// Flash attention v5 (R9 data paths) + PDL sync/trigger.
// ---------------------------------------------------------------------------
#define FSK 72
#define FSV 72
#define FSP 68
#define KBUF (64*FSK)
#define VBUF (64*FSV)
#define FL_SMF (2*KBUF + 2*VBUF + 128*FSP)

__global__ __launch_bounds__(256, 2) void flash_tc5(const float* __restrict__ qkv,
                                                    float* __restrict__ attn) {
    extern __shared__ float sm[];
    float* Ks = sm;
    float* Vs = sm + 2 * KBUF;
    float* Ps = sm + 2 * KBUF + 2 * VBUF;

    cudaGridDependencySynchronize();
    cudaTriggerProgrammaticLaunchCompletion();

    const int tid = threadIdx.x;
    const int wid = tid >> 5, lane = tid & 31;
    const int g = lane >> 2, tg = lane & 3;
    const int qr = wid * 16;
    const int qt = blockIdx.x;
    const int bh = blockIdx.y;
    const int b = bh >> 4, h = bh & 15;
    const size_t base = (size_t)b * SEQ;
    const int qoff = h * DHEAD;
    const int koff = DIMN + h * DHEAD;
    const int voff = 2 * DIMN + h * DHEAD;

    #pragma unroll
    for (int p = 0; p < 8; p++) {
        int idx = tid + p * 256;
        int row = idx >> 4, c4 = (idx & 15) * 4;
        *(float4*)(Ps + row * FSP + c4) =
            *(const float4*)(qkv + (base + qt * 128 + row) * QKV_N + qoff + c4);
    }
    __syncthreads();
    unsigned qf[8][4];
    {
        const float QS = 0.125f * 1.4426950408889634f;
        const int r0 = (qr + g) * FSP, r1 = (qr + g + 8) * FSP;
        #pragma unroll
        for (int ks = 0; ks < 8; ks++) {
            int c = ks * 8 + tg;
            qf[ks][0] = f2tf(Ps[r0 + c]     * QS);
            qf[ks][1] = f2tf(Ps[r1 + c]     * QS);
            qf[ks][2] = f2tf(Ps[r0 + c + 4] * QS);
            qf[ks][3] = f2tf(Ps[r1 + c + 4] * QS);
        }
    }

    auto loadKV = [&](int buf, int kt) {
        unsigned kbase = (unsigned)__cvta_generic_to_shared(Ks + buf * KBUF);
        unsigned vbase = (unsigned)__cvta_generic_to_shared(Vs + buf * VBUF);
        #pragma unroll
        for (int p = 0; p < 4; p++) {
            int idx = tid + p * 256;
            int row = idx >> 4, c4 = (idx & 15) * 4;
            const float* rp = qkv + (base + kt * 64 + row) * QKV_N;
            CP_ASYNC16(kbase + (row * FSK + c4) * 4, rp + koff + c4);
            CP_ASYNC16(vbase + (row * FSV + c4) * 4, rp + voff + c4);
        }
    };

    float l[2] = {0.f, 0.f};
    float c[4][2][4] = {};

    const int NT = SEQ / 64;
    loadKV(0, 0);
    asm volatile("cp.async.commit_group;\n");

    for (int kt = 0; kt < NT; kt++) {
        asm volatile("cp.async.wait_group 0;\n");
        __syncthreads();
        if (kt + 1 < NT) {
            loadKV((kt + 1) & 1, kt + 1);
            asm volatile("cp.async.commit_group;\n");
        }

        const float* Kb = Ks + (kt & 1) * KBUF;
        const float* Vb = Vs + (kt & 1) * VBUF;

        float sc[8][4] = {};
        #pragma unroll
        for (int ks = 0; ks < 8; ks++) {
            const int kk = ks * 8;
            #pragma unroll
            for (int nt = 0; nt < 8; nt++) {
                float2 bb = *(const float2*)&Kb[(nt * 8 + g) * FSK + kk + 2 * tg];
                mma_tf32(sc[nt][0], sc[nt][1], sc[nt][2], sc[nt][3],
                         qf[ks][0], qf[ks][1], qf[ks][2], qf[ks][3],
                         __float_as_uint(bb.x), __float_as_uint(bb.y));
            }
        }

        #pragma unroll
        for (int rh = 0; rh < 2; rh++) {
            float rs = 0.f;
            int prow = (qr + g + 8 * rh) * FSP;
            #pragma unroll
            for (int nt = 0; nt < 8; nt++) {
                float p0 = __uint_as_float(f2tf(fex2(sc[nt][2 * rh])));
                float p1 = __uint_as_float(f2tf(fex2(sc[nt][2 * rh + 1])));
                rs += p0 + p1;
                *(float2*)(Ps + prow + nt * 8 + 2 * tg) = make_float2(p0, p1);
            }
            rs += __shfl_xor_sync(0xffffffffu, rs, 1);
            rs += __shfl_xor_sync(0xffffffffu, rs, 2);
            l[rh] += rs;
        }
        __syncwarp();

        #pragma unroll
        for (int ks = 0; ks < 8; ks++) {
            const int kk = ks * 8;
            unsigned pb[2][2];
            #pragma unroll
            for (int nh = 0; nh < 2; nh++) {
                pb[nh][0] = __float_as_uint(Ps[(qr + nh * 8 + g) * FSP + kk + tg]);
                pb[nh][1] = __float_as_uint(Ps[(qr + nh * 8 + g) * FSP + kk + tg + 4]);
            }
            #pragma unroll
            for (int mt = 0; mt < 4; mt++) {
                float2 va0 = *(const float2*)&Vb[(kk + tg)     * FSV + mt * 16 + 2 * g];
                float2 va1 = *(const float2*)&Vb[(kk + tg + 4) * FSV + mt * 16 + 2 * g];
                #pragma unroll
                for (int nh = 0; nh < 2; nh++)
                    mma_tf32(c[mt][nh][0], c[mt][nh][1], c[mt][nh][2], c[mt][nh][3],
                             __float_as_uint(va0.x), __float_as_uint(va0.y),
                             __float_as_uint(va1.x), __float_as_uint(va1.y),
                             pb[nh][0], pb[nh][1]);
            }
        }
        __syncwarp();
    }

    float linv[2][2];
    #pragma unroll
    for (int nh = 0; nh < 2; nh++) {
        linv[nh][0] = 1.f / __shfl_sync(0xffffffffu, l[nh], 8 * tg);
        linv[nh][1] = 1.f / __shfl_sync(0xffffffffu, l[nh], 8 * tg + 4);
    }
    #pragma unroll
    for (int mt = 0; mt < 4; mt++) {
        #pragma unroll
        for (int nh = 0; nh < 2; nh++) {
            int q = qt * 128 + qr + nh * 8 + 2 * tg;
            int d0 = mt * 16 + g;
            size_t ro = (base + q) * (size_t)DIMN + h * DHEAD;
            attn[ro + d0]            = __uint_as_float(f2tf(c[mt][nh][0] * linv[nh][0]));
            attn[ro + DIMN + d0]     = __uint_as_float(f2tf(c[mt][nh][1] * linv[nh][1]));
            attn[ro + d0 + 8]        = __uint_as_float(f2tf(c[mt][nh][2] * linv[nh][0]));
            attn[ro + DIMN + d0 + 8] = __uint_as_float(f2tf(c[mt][nh][3] * linv[nh][1]));
        }
    }
}

// ---------------------------------------------------------------------------
// Launch: single stream; PDL edges prep -> gemm1 -> flash -> gemm2.
// No streams, no events, no allocations.
// ---------------------------------------------------------------------------
extern "C" void kernel_launch(void* const* d_in, const int* in_sizes, int n_in,
                              void* d_out, int out_size)
{
    const float* x      = (const float*)d_in[0];
    const float* gamma  = (const float*)d_in[1];
    const float* beta   = (const float*)d_in[2];
    const float* w_qkv  = (const float*)d_in[3];
    const float* w_out  = (const float*)d_in[4];
    const float* b_out  = (const float*)d_in[5];
    float* out = (float*)d_out;

    float *xn, *qkvp, *attnp, *wq, *wo;
    cudaGetSymbolAddress((void**)&xn,    g_xn);
    cudaGetSymbolAddress((void**)&qkvp,  g_qkv);
    cudaGetSymbolAddress((void**)&attnp, g_attn);
    cudaGetSymbolAddress((void**)&wq,    g_wq);
    cudaGetSymbolAddress((void**)&wo,    g_wo);

    const int gemm_smem  = 3 * STG * sizeof(float);     // 107520
    const int flash_smem = FL_SMF * sizeof(float);      // 108544
    cudaFuncSetAttribute(gemm_tc,   cudaFuncAttributeMaxDynamicSharedMemorySize, gemm_smem);
    cudaFuncSetAttribute(flash_tc5, cudaFuncAttributeMaxDynamicSharedMemorySize, flash_smem);

    cudaLaunchAttribute pdl[1];
    pdl[0].id = cudaLaunchAttributeProgrammaticStreamSerialization;
    pdl[0].val.programmaticStreamSerializationAllowed = 1;

    // prep (normal launch; triggers early for gemm1's programmatic start)
    prep_kernel<<<PREP_BLKS, 256>>>(w_qkv, w_out, x, gamma, beta);

    // gemm1 (PDL consumer of prep)
    {
        cudaLaunchConfig_t cfg = {};
        cfg.gridDim = dim3(QKV_N / 128, ROWS / 128);
        cfg.blockDim = dim3(256);
        cfg.dynamicSmemBytes = gemm_smem;
        cfg.stream = 0;
        cfg.attrs = pdl;
        cfg.numAttrs = 1;
        cudaLaunchKernelEx(&cfg, gemm_tc, (const float*)xn, (const float*)wq,
                           (const float*)nullptr, qkvp, ROWS, QKV_N, DIMN, 1);
    }

    // flash (PDL consumer of gemm1)
    {
        cudaLaunchConfig_t cfg = {};
        cfg.gridDim = dim3(SEQ / 128, BATCH * HEADS);
        cfg.blockDim = dim3(256);
        cfg.dynamicSmemBytes = flash_smem;
        cfg.stream = 0;
        cfg.attrs = pdl;
        cfg.numAttrs = 1;
        cudaLaunchKernelEx(&cfg, flash_tc5, (const float*)qkvp, attnp);
    }

    // gemm2 (PDL consumer of flash)
    {
        cudaLaunchConfig_t cfg = {};
        cfg.gridDim = dim3(DIMN / 128, ROWS / 128);
        cfg.blockDim = dim3(256);
        cfg.dynamicSmemBytes = gemm_smem;
        cfg.stream = 0;
        cfg.attrs = pdl;
        cfg.numAttrs = 1;
        cudaLaunchKernelEx(&cfg, gemm_tc, (const float*)attnp, (const float*)wo,
                           b_out, out, ROWS, DIMN, DIMN, 0);
    }
}

// round 13
// speedup vs baseline: 1.1403x; 1.0829x over previous
#include <cuda_runtime.h>
#include <math.h>

#define BATCH 4
#define SEQ   2048
#define DIMN  1024
#define HEADS 16
#define DHEAD 64
#define ROWS  (BATCH*SEQ)      /* 8192 */
#define QKV_N (3*DIMN)         /* 3072 */

// Scratch (allocation-free rule: __device__ globals)
static __device__ float g_xn[(size_t)ROWS*DIMN];
static __device__ float g_qkv[(size_t)ROWS*QKV_N];   // K cols perm8'd, V cols perm16'd
static __device__ float g_attn[(size_t)ROWS*DIMN];
static __device__ float g_wq[(size_t)DIMN*QKV_N];
static __device__ float g_wo[(size_t)DIMN*DIMN];
// progress counters (decoupled lookback between fused stages)
static __device__ int   g_cnt1[64];   // qkv row-tiles (128 rows): target 24
static __device__ int   g_cnt2[64];   // attn row-tiles (128 rows): target 16

// ---------------------------------------------------------------------------
__device__ __forceinline__ unsigned f2tf(float x) {
    unsigned r;
    asm("cvt.rna.tf32.f32 %0, %1;" : "=r"(r) : "f"(x));
    return r;
}

__device__ __forceinline__ float fex2(float x) {   // 2^x, clamped below
    float r;
    x = fmaxf(x, -126.f);
    asm("ex2.approx.ftz.f32 %0, %1;" : "=f"(r) : "f"(x));
    return r;
}

__device__ __forceinline__ int permcol(int c) {
    int reg = c >> 10;
    if (reg == 1) return (c & ~7)  | ((c & 3) << 1) | ((c >> 2) & 1);
    if (reg == 2) return (c & ~15) | ((c & 7) << 1) | ((c >> 3) & 1);
    return c;
}

__device__ __forceinline__ void mma_tf32(float& c0, float& c1, float& c2, float& c3,
                                         unsigned a0, unsigned a1, unsigned a2, unsigned a3,
                                         unsigned b0, unsigned b1) {
    asm volatile(
        "mma.sync.aligned.m16n8k8.row.col.f32.tf32.tf32.f32 "
        "{%0,%1,%2,%3}, {%4,%5,%6,%7}, {%8,%9}, {%0,%1,%2,%3};\n"
        : "+f"(c0), "+f"(c1), "+f"(c2), "+f"(c3)
        : "r"(a0), "r"(a1), "r"(a2), "r"(a3), "r"(b0), "r"(b1));
}

#define CP_ASYNC16(dst, src) \
    asm volatile("cp.async.cg.shared.global [%0], [%1], 16;\n" :: "r"(dst), "l"(src))

// classic flag wait: producer did __threadfence()+atomicAdd (release);
// consumer polls volatile then __threadfence() (acquire).
__device__ __forceinline__ void waitcnt(const int* c, int target) {
    if (*(volatile const int*)c < target) {
        while (*(volatile const int*)c < target) __nanosleep(128);
    }
    __threadfence();
}

// ---------------------------------------------------------------------------
// prep: zero counters + wq cvt (blocks 0..3071) + wo cvt + ln
// ---------------------------------------------------------------------------
#define PREP_WQ_BLKS 3072
#define PREP_WO_BLKS 1024
#define PREP_BLKS    (PREP_WQ_BLKS + PREP_WO_BLKS + ROWS)

__global__ __launch_bounds__(256) void prep_kernel(const float* __restrict__ w_qkv,
                                                   const float* __restrict__ w_out,
                                                   const float* __restrict__ x,
                                                   const float* __restrict__ gamma,
                                                   const float* __restrict__ beta) {
    cudaTriggerProgrammaticLaunchCompletion();
    const int blk = blockIdx.x;
    const int t = threadIdx.x;

    if (blk == 0 && t < 64) { g_cnt1[t] = 0; g_cnt2[t] = 0; }

    if (blk < PREP_WQ_BLKS + PREP_WO_BLKS) {
        const float* src = (blk < PREP_WQ_BLKS) ? w_qkv : w_out;
        float* dst       = (blk < PREP_WQ_BLKS) ? g_wq  : g_wo;
        int i = (blk < PREP_WQ_BLKS ? blk : blk - PREP_WQ_BLKS) * 256 + t;
        float4 v = ((const float4*)src)[i];
        uint4 o;
        o.x = f2tf(v.x); o.y = f2tf(v.y); o.z = f2tf(v.z); o.w = f2tf(v.w);
        ((uint4*)dst)[i] = o;
        return;
    }

    __shared__ float red[16];
    const int row = blk - (PREP_WQ_BLKS + PREP_WO_BLKS);
    const float* xr = x + (size_t)row * DIMN;
    float4 v = *(const float4*)(xr + t * 4);
    float s = v.x + v.y + v.z + v.w;
    float q = v.x*v.x + v.y*v.y + v.z*v.z + v.w*v.w;
    #pragma unroll
    for (int o = 16; o; o >>= 1) {
        s += __shfl_xor_sync(0xffffffffu, s, o);
        q += __shfl_xor_sync(0xffffffffu, q, o);
    }
    if ((t & 31) == 0) { red[t >> 5] = s; red[8 + (t >> 5)] = q; }
    __syncthreads();
    if (t < 32) {
        float ss = (t < 8) ? red[t] : 0.f;
        float qq = (t < 8) ? red[8 + t] : 0.f;
        #pragma unroll
        for (int o = 4; o; o >>= 1) {
            ss += __shfl_xor_sync(0xffffffffu, ss, o);
            qq += __shfl_xor_sync(0xffffffffu, qq, o);
        }
        if (t == 0) { red[0] = ss; red[1] = qq; }
    }
    __syncthreads();
    const float mean = red[0] * (1.f / DIMN);
    const float var  = red[1] * (1.f / DIMN) - mean * mean;
    const float inv  = rsqrtf(var + 1e-5f);
    float4 g = *(const float4*)(gamma + t * 4);
    float4 b = *(const float4*)(beta  + t * 4);
    uint4 o4;
    o4.x = f2tf((v.x - mean) * inv * g.x + b.x);
    o4.y = f2tf((v.y - mean) * inv * g.y + b.y);
    o4.z = f2tf((v.z - mean) * inv * g.z + b.z);
    o4.w = f2tf((v.w - mean) * inv * g.w + b.w);
    *(uint4*)(g_xn + (size_t)row * DIMN + t * 4) = o4;
}

// ---------------------------------------------------------------------------
// GEMM body (R12, proven): 3-stage cp.async pipeline, one barrier per K-tile.
// ---------------------------------------------------------------------------
#define ASTR 36
#define BSTR 136
#define ABUF (128*ASTR)
#define BBUF (32*BSTR)
#define STG  (ABUF+BBUF)

__device__ __forceinline__ void gemm_body(const float* __restrict__ A,
                                          const float* __restrict__ B,
                                          const float* __restrict__ bias,
                                          float* __restrict__ C,
                                          int N, int K, int mode,
                                          int bm, int bn, float* sm) {
    const int tid = threadIdx.x;
    const int wid = tid >> 5, lane = tid & 31;
    const int g = lane >> 2, tg = lane & 3;
    const int wm = wid >> 1, wn = wid & 1;

    float c[2][8][4] = {};

    auto loadAB = [&](int buf, int k0) {
        float* As = sm + buf * STG;
        float* Bs = As + ABUF;
        unsigned abase = (unsigned)__cvta_generic_to_shared(As);
        unsigned bbase = (unsigned)__cvta_generic_to_shared(Bs);
        #pragma unroll
        for (int p = 0; p < 4; p++) {
            int idx = tid + p * 256;
            int ar = idx >> 3, ac = (idx & 7) * 4;
            CP_ASYNC16(abase + (ar * ASTR + ac) * 4, A + (size_t)(bm + ar) * K + k0 + ac);
            int br = idx >> 5, bc = (idx & 31) * 4;
            CP_ASYNC16(bbase + (br * BSTR + bc) * 4, B + (size_t)(k0 + br) * N + bn + bc);
        }
    };

    const int nk = K / 32;
    loadAB(0, 0);
    asm volatile("cp.async.commit_group;\n");
    loadAB(1, 32);
    asm volatile("cp.async.commit_group;\n");

    int cur = 0, nxt = 2;
    for (int kb = 0; kb < nk; kb++) {
        if (kb + 1 < nk) {
            asm volatile("cp.async.wait_group 1;\n");
        } else {
            asm volatile("cp.async.wait_group 0;\n");
        }
        __syncthreads();
        if (kb + 2 < nk) {
            loadAB(nxt, (kb + 2) * 32);
            asm volatile("cp.async.commit_group;\n");
        }

        const float* Ab = sm + cur * STG;
        const float* Bb = Ab + ABUF;
        #pragma unroll
        for (int ks = 0; ks < 4; ks++) {
            const int kk = ks * 8;
            unsigned a[2][4], b[8][2];
            #pragma unroll
            for (int mt = 0; mt < 2; mt++) {
                int r0 = wm * 32 + mt * 16;
                a[mt][0] = __float_as_uint(Ab[(r0 + g)     * ASTR + kk + tg]);
                a[mt][1] = __float_as_uint(Ab[(r0 + g + 8) * ASTR + kk + tg]);
                a[mt][2] = __float_as_uint(Ab[(r0 + g)     * ASTR + kk + tg + 4]);
                a[mt][3] = __float_as_uint(Ab[(r0 + g + 8) * ASTR + kk + tg + 4]);
            }
            #pragma unroll
            for (int nt = 0; nt < 8; nt++) {
                int col = wn * 64 + nt * 8 + g;
                b[nt][0] = __float_as_uint(Bb[(kk + tg)     * BSTR + col]);
                b[nt][1] = __float_as_uint(Bb[(kk + tg + 4) * BSTR + col]);
            }
            #pragma unroll
            for (int mt = 0; mt < 2; mt++)
                #pragma unroll
                for (int nt = 0; nt < 8; nt++)
                    mma_tf32(c[mt][nt][0], c[mt][nt][1], c[mt][nt][2], c[mt][nt][3],
                             a[mt][0], a[mt][1], a[mt][2], a[mt][3],
                             b[nt][0], b[nt][1]);
        }
        cur = (cur == 2) ? 0 : cur + 1;
        nxt = (nxt == 2) ? 0 : nxt + 1;
    }

    #pragma unroll
    for (int mt = 0; mt < 2; mt++) {
        int r0 = bm + wm * 32 + mt * 16 + g;
        #pragma unroll
        for (int nt = 0; nt < 8; nt++) {
            int col = bn + wn * 64 + nt * 8 + 2 * tg;
            if (mode == 0) {
                float b0 = bias ? bias[col] : 0.f, b1 = bias ? bias[col + 1] : 0.f;
                *(float2*)(C + (size_t)r0 * N + col) =
                    make_float2(c[mt][nt][0] + b0, c[mt][nt][1] + b1);
                *(float2*)(C + (size_t)(r0 + 8) * N + col) =
                    make_float2(c[mt][nt][2] + b0, c[mt][nt][3] + b1);
            } else {
                int c0 = permcol(col), c1 = permcol(col + 1);
                C[(size_t)r0 * N + c0]       = __uint_as_float(f2tf(c[mt][nt][0]));
                C[(size_t)r0 * N + c1]       = __uint_as_float(f2tf(c[mt][nt][1]));
                C[(size_t)(r0 + 8) * N + c0] = __uint_as_float(f2tf(c[mt][nt][2]));
                C[(size_t)(r0 + 8) * N + c1] = __uint_as_float(f2tf(c[mt][nt][3]));
            }
        }
    }
}

// ---------------------------------------------------------------------------
// Flash body (R12 data paths) with per-tile producer waits on g_cnt1.
// ---------------------------------------------------------------------------
#define FSK 72
#define FSV 72
#define FSP 68
#define KBUF (64*FSK)
#define VBUF (64*FSV)
#define FL_SMF (2*KBUF + 2*VBUF + 128*FSP)    /* 27136 floats = 108544 B */

__device__ __forceinline__ void flash_body(int qt, int b, int h, float* sm) {
    float* Ks = sm;
    float* Vs = sm + 2 * KBUF;
    float* Ps = sm + 2 * KBUF + 2 * VBUF;

    const int tid = threadIdx.x;
    const int wid = tid >> 5, lane = tid & 31;
    const int g = lane >> 2, tg = lane & 3;
    const int qr = wid * 16;
    const size_t base = (size_t)b * SEQ;
    const int qoff = h * DHEAD;
    const int koff = DIMN + h * DHEAD;
    const int voff = 2 * DIMN + h * DHEAD;
    const float* qkv = g_qkv;
    const int ct0 = b * 16;

    // wait for our Q row-tile, then stage Q
    waitcnt(&g_cnt1[ct0 + qt], 24);
    #pragma unroll
    for (int p = 0; p < 8; p++) {
        int idx = tid + p * 256;
        int row = idx >> 4, c4 = (idx & 15) * 4;
        *(float4*)(Ps + row * FSP + c4) =
            *(const float4*)(qkv + (base + qt * 128 + row) * QKV_N + qoff + c4);
    }
    __syncthreads();
    unsigned qf[8][4];
    {
        const float QS = 0.125f * 1.4426950408889634f;
        const int r0 = (qr + g) * FSP, r1 = (qr + g + 8) * FSP;
        #pragma unroll
        for (int ks = 0; ks < 8; ks++) {
            int c = ks * 8 + tg;
            qf[ks][0] = f2tf(Ps[r0 + c]     * QS);
            qf[ks][1] = f2tf(Ps[r1 + c]     * QS);
            qf[ks][2] = f2tf(Ps[r0 + c + 4] * QS);
            qf[ks][3] = f2tf(Ps[r1 + c + 4] * QS);
        }
    }

    auto loadKV = [&](int buf, int kt) {
        unsigned kbase = (unsigned)__cvta_generic_to_shared(Ks + buf * KBUF);
        unsigned vbase = (unsigned)__cvta_generic_to_shared(Vs + buf * VBUF);
        #pragma unroll
        for (int p = 0; p < 4; p++) {
            int idx = tid + p * 256;
            int row = idx >> 4, c4 = (idx & 15) * 4;
            const float* rp = qkv + (base + kt * 64 + row) * QKV_N;
            CP_ASYNC16(kbase + (row * FSK + c4) * 4, rp + koff + c4);
            CP_ASYNC16(vbase + (row * FSV + c4) * 4, rp + voff + c4);
        }
    };

    int kvw = -1;   // watermark over confirmed KV row-tiles (uniform)
    auto wait_kv = [&](int j) {
        if (j > kvw) { waitcnt(&g_cnt1[ct0 + j], 24); kvw = j; }
    };

    float l[2] = {0.f, 0.f};
    float c[4][2][4] = {};

    const int NT = SEQ / 64;
    wait_kv(0);
    loadKV(0, 0);
    asm volatile("cp.async.commit_group;\n");

    for (int kt = 0; kt < NT; kt++) {
        asm volatile("cp.async.wait_group 0;\n");
        __syncthreads();
        if (kt + 1 < NT) {
            wait_kv((kt + 1) >> 1);
            loadKV((kt + 1) & 1, kt + 1);
            asm volatile("cp.async.commit_group;\n");
        }

        const float* Kb = Ks + (kt & 1) * KBUF;
        const float* Vb = Vs + (kt & 1) * VBUF;

        float sc[8][4] = {};
        #pragma unroll
        for (int ks = 0; ks < 8; ks++) {
            const int kk = ks * 8;
            #pragma unroll
            for (int nt = 0; nt < 8; nt++) {
                float2 bb = *(const float2*)&Kb[(nt * 8 + g) * FSK + kk + 2 * tg];
                mma_tf32(sc[nt][0], sc[nt][1], sc[nt][2], sc[nt][3],
                         qf[ks][0], qf[ks][1], qf[ks][2], qf[ks][3],
                         __float_as_uint(bb.x), __float_as_uint(bb.y));
            }
        }

        #pragma unroll
        for (int rh = 0; rh < 2; rh++) {
            float rs = 0.f;
            int prow = (qr + g + 8 * rh) * FSP;
            #pragma unroll
            for (int nt = 0; nt < 8; nt++) {
                float p0 = __uint_as_float(f2tf(fex2(sc[nt][2 * rh])));
                float p1 = __uint_as_float(f2tf(fex2(sc[nt][2 * rh + 1])));
                rs += p0 + p1;
                *(float2*)(Ps + prow + nt * 8 + 2 * tg) = make_float2(p0, p1);
            }
            rs += __shfl_xor_sync(0xffffffffu, rs, 1);
            rs += __shfl_xor_sync(0xffffffffu, rs, 2);
            l[rh] += rs;
        }
        __syncwarp();

        #pragma unroll
        for (int ks = 0; ks < 8; ks++) {
            const int kk = ks * 8;
            unsigned pb[2][2];
            #pragma unroll
            for (int nh = 0; nh < 2; nh++) {
                pb[nh][0] = __float_as_uint(Ps[(qr + nh * 8 + g) * FSP + kk + tg]);
                pb[nh][1] = __float_as_uint(Ps[(qr + nh * 8 + g) * FSP + kk + tg + 4]);
            }
            #pragma unroll
            for (int mt = 0; mt < 4; mt++) {
                float2 va0 = *(const float2*)&Vb[(kk + tg)     * FSV + mt * 16 + 2 * g];
                float2 va1 = *(const float2*)&Vb[(kk + tg + 4) * FSV + mt * 16 + 2 * g];
                #pragma unroll
                for (int nh = 0; nh < 2; nh++)
                    mma_tf32(c[mt][nh][0], c[mt][nh][1], c[mt][nh][2], c[mt][nh][3],
                             __float_as_uint(va0.x), __float_as_uint(va0.y),
                             __float_as_uint(va1.x), __float_as_uint(va1.y),
                             pb[nh][0], pb[nh][1]);
            }
        }
        __syncwarp();
    }

    float linv[2][2];
    #pragma unroll
    for (int nh = 0; nh < 2; nh++) {
        linv[nh][0] = 1.f / __shfl_sync(0xffffffffu, l[nh], 8 * tg);
        linv[nh][1] = 1.f / __shfl_sync(0xffffffffu, l[nh], 8 * tg + 4);
    }
    #pragma unroll
    for (int mt = 0; mt < 4; mt++) {
        #pragma unroll
        for (int nh = 0; nh < 2; nh++) {
            int q = qt * 128 + qr + nh * 8 + 2 * tg;
            int d0 = mt * 16 + g;
            size_t ro = (base + q) * (size_t)DIMN + h * DHEAD;
            g_attn[ro + d0]            = __uint_as_float(f2tf(c[mt][nh][0] * linv[nh][0]));
            g_attn[ro + DIMN + d0]     = __uint_as_float(f2tf(c[mt][nh][1] * linv[nh][1]));
            g_attn[ro + d0 + 8]        = __uint_as_float(f2tf(c[mt][nh][2] * linv[nh][0]));
            g_attn[ro + DIMN + d0 + 8] = __uint_as_float(f2tf(c[mt][nh][3] * linv[nh][1]));
        }
    }
}

// ---------------------------------------------------------------------------
// Fused kernel: gemm1 (0..1535, bm-major) | flash (1536..2559) | gemm2 (..3071)
// ---------------------------------------------------------------------------
#define G1 1536
#define G2 1024
#define G3 512
#define FUSED_SMEM 108544

__global__ __launch_bounds__(256, 2) void fused_kernel(const float* __restrict__ b_out,
                                                       float* __restrict__ out) {
    extern __shared__ float sm[];
    cudaGridDependencySynchronize();       // prep done (xn, weights, counters=0)
    cudaTriggerProgrammaticLaunchCompletion();

    const int bid = blockIdx.x;
    const int tid = threadIdx.x;

    if (bid < G1) {
        // gemm1: bm-major so qkv row-tiles complete in order
        const int bm = (bid / 24) * 128, bn = (bid % 24) * 128;
        gemm_body(g_xn, g_wq, nullptr, g_qkv, QKV_N, DIMN, 1, bm, bn, sm);
        __syncthreads();
        if (tid == 0) { __threadfence(); atomicAdd(&g_cnt1[bm >> 7], 1); }
    } else if (bid < G1 + G2) {
        // flash: batch-major, qt next, head fastest
        const int f = bid - G1;
        const int b = f >> 8, r = f & 255, qt = r >> 4, h = r & 15;
        flash_body(qt, b, h, sm);
        __syncthreads();
        if (tid == 0) { __threadfence(); atomicAdd(&g_cnt2[b * 16 + qt], 1); }
    } else {
        // gemm2: bm-major; waits for all 16 heads of its attn row-tile
        const int z = bid - G1 - G2;
        const int bm = (z >> 3) * 128, bn = (z & 7) * 128;
        waitcnt(&g_cnt2[bm >> 7], 16);
        gemm_body(g_attn, g_wo, b_out, out, DIMN, DIMN, 0, bm, bn, sm);
    }
}

// ---------------------------------------------------------------------------
extern "C" void kernel_launch(void* const* d_in, const int* in_sizes, int n_in,
                              void* d_out, int out_size)
{
    const float* x      = (const float*)d_in[0];
    const float* gamma  = (const float*)d_in[1];
    const float* beta   = (const float*)d_in[2];
    const float* w_qkv  = (const float*)d_in[3];
    const float* w_out  = (const float*)d_in[4];
    const float* b_out  = (const float*)d_in[5];
    float* out = (float*)d_out;

    cudaFuncSetAttribute(fused_kernel, cudaFuncAttributeMaxDynamicSharedMemorySize,
                         FUSED_SMEM);

    cudaLaunchAttribute pdl[1];
    pdl[0].id = cudaLaunchAttributeProgrammaticStreamSerialization;
    pdl[0].val.programmaticStreamSerializationAllowed = 1;

    prep_kernel<<<PREP_BLKS, 256>>>(w_qkv, w_out, x, gamma, beta);

    cudaLaunchConfig_t cfg = {};
    cfg.gridDim = dim3(G1 + G2 + G3);
    cfg.blockDim = dim3(256);
    cfg.dynamicSmemBytes = FUSED_SMEM;
    cfg.stream = 0;
    cfg.attrs = pdl;
    cfg.numAttrs = 1;
    cudaLaunchKernelEx(&cfg, fused_kernel, b_out, out);
}